// round 8
// baseline (speedup 1.0000x reference)
#include <cuda_runtime.h>
#include <math.h>

// Problem constants
#define S2      2
#define CDIM    256
#define KD      128
#define CE      16
#define NF      5
#define HW      2304               // 48*48
#define LQ      2304
#define LK      11520              // 5*2304
#define NSPLIT  8
#define KTILES  (LK / 64)          // 180 key tiles of 64

// ---------------- scratch (static device memory; no cudaMalloc allowed) ----
__device__ float g_tgtT[S2 * LQ * CDIM];
__device__ float g_memT[S2 * LK * CDIM];
__device__ float g_posT[S2 * LK * CE];
__device__ float g_wqs [S2 * LQ * KD];
__device__ float g_wvs [S2 * LQ * CDIM];
__device__ float g_wvsT[S2 * CDIM * LQ];
__device__ float g_Ss  [(size_t)S2 * LQ * LQ];   // self exp-scores (~42MB)
__device__ float g_lself[S2 * LQ];
__device__ float g_x   [S2 * LQ * CDIM];
__device__ float g_mu  [S2 * CDIM];
__device__ float g_rstd[S2 * CDIM];
__device__ float g_wqc [S2 * LQ * KD];
__device__ float g_wkc [S2 * LK * KD];
__device__ float g_wvc [S2 * LK * CE];
__device__ float g_po  [S2 * NSPLIT * LQ * CE];  // cross partial outputs (unnormalized)
__device__ float g_pl  [S2 * NSPLIT * LQ];       // cross partial row sums

// ---------------- f32x2 packed FMA helpers ----------------------------------
union F2u { float2 f; unsigned long long u; };

__device__ __forceinline__ unsigned long long pk(float x, float y) {
    F2u t; t.f.x = x; t.f.y = y; return t.u;
}
__device__ __forceinline__ void fma2(unsigned long long& acc,
                                     unsigned long long a, unsigned long long b) {
    asm("fma.rn.f32x2 %0, %1, %2, %0;" : "+l"(acc) : "l"(a), "l"(b));
}
__device__ __forceinline__ float unpk_sum(unsigned long long v) {
    F2u t; t.u = v; return t.f.x + t.f.y;
}

// ---------------- tiled transpose: in [R][Cc] -> out [Cc][R], batched --------
__global__ void transpose_k(const float* __restrict__ in, float* __restrict__ out,
                            int R, int Cc, size_t inZ, size_t outS, size_t outF,
                            int mods) {
    __shared__ float tile[32][33];
    int z = blockIdx.z;
    in  += (size_t)z * inZ;
    out += (size_t)(z % mods) * outS + (size_t)(z / mods) * outF;
    int c0 = blockIdx.x * 32;
    int r0 = blockIdx.y * 32;
    int tx = threadIdx.x, ty = threadIdx.y;          // 32 x 8
    #pragma unroll
    for (int i = ty; i < 32; i += 8) {
        int r = r0 + i, c = c0 + tx;
        if (r < R && c < Cc) tile[i][tx] = in[(size_t)r * Cc + c];
    }
    __syncthreads();
    #pragma unroll
    for (int i = ty; i < 32; i += 8) {
        int c = c0 + i, r = r0 + tx;
        if (r < R && c < Cc) out[(size_t)c * R + r] = tile[tx][i];
    }
}

// ---------------- GEMM: C[M,N] = A[M,K]*B[N,K]^T with fused epilogues --------
// 128x64 tile, 256 threads, 8x4 micro (strided), f32x2 packed along K.
// epilogue: (+bias[col]) -> (exp(30x)) -> (/rowdiv[row]) -> (+resid[row][col])
__global__ void __launch_bounds__(256) gemm_nt(
    const float* __restrict__ A, const float* __restrict__ B,
    const float* __restrict__ bias, const float* __restrict__ resid,
    const float* __restrict__ rowdiv, float* __restrict__ C,
    int M, int N, int K, int do_exp,
    size_t sA, size_t sB, size_t sC, size_t sR, size_t sD) {
    int z = blockIdx.z;
    A += (size_t)z * sA;
    B += (size_t)z * sB;
    C += (size_t)z * sC;
    if (resid)  resid  += (size_t)z * sR;
    if (rowdiv) rowdiv += (size_t)z * sD;

    __shared__ float As[128][36];   // 32 K-floats + 4 pad (9 quads, odd -> conflict-free)
    __shared__ float Bs[64][36];

    const int t  = threadIdx.x;
    const int tx = t & 15, ty = t >> 4;
    const int row0 = blockIdx.y * 128, col0 = blockIdx.x * 64;
    const int c8 = (t & 7) * 4, rr = t >> 3;

    unsigned long long acc[8][4];
    #pragma unroll
    for (int i = 0; i < 8; i++)
        #pragma unroll
        for (int j = 0; j < 4; j++) acc[i][j] = 0ull;

    for (int k0 = 0; k0 < K; k0 += 32) {
        #pragma unroll
        for (int r = rr; r < 128; r += 32)
            *(float4*)&As[r][c8] = *(const float4*)&A[(size_t)(row0 + r) * K + k0 + c8];
        #pragma unroll
        for (int r = rr; r < 64; r += 32)
            *(float4*)&Bs[r][c8] = *(const float4*)&B[(size_t)(col0 + r) * K + k0 + c8];
        __syncthreads();
        #pragma unroll
        for (int kc = 0; kc < 32; kc += 4) {
            float4 av[8], bv[4];
            #pragma unroll
            for (int i = 0; i < 8; i++) av[i] = *(float4*)&As[ty + 16 * i][kc];
            #pragma unroll
            for (int j = 0; j < 4; j++) bv[j] = *(float4*)&Bs[tx + 16 * j][kc];
            unsigned long long b01[4], b23[4];
            #pragma unroll
            for (int j = 0; j < 4; j++) {
                b01[j] = pk(bv[j].x, bv[j].y);
                b23[j] = pk(bv[j].z, bv[j].w);
            }
            #pragma unroll
            for (int i = 0; i < 8; i++) {
                unsigned long long a01 = pk(av[i].x, av[i].y);
                unsigned long long a23 = pk(av[i].z, av[i].w);
                #pragma unroll
                for (int j = 0; j < 4; j++) {
                    fma2(acc[i][j], a01, b01[j]);
                    fma2(acc[i][j], a23, b23[j]);
                }
            }
        }
        __syncthreads();
    }

    #pragma unroll
    for (int i = 0; i < 8; i++) {
        int r = row0 + ty + 16 * i;
        float inv = rowdiv ? (1.0f / rowdiv[r]) : 1.0f;
        #pragma unroll
        for (int j = 0; j < 4; j++) {
            int c = col0 + tx + 16 * j;
            float v = unpk_sum(acc[i][j]);
            if (bias) v += bias[c];
            if (do_exp) v = __expf(30.0f * v);
            v *= inv;
            if (resid) v += resid[(size_t)r * N + c];
            C[(size_t)r * N + c] = v;
        }
    }
}

// ---------------- row ops ----------------------------------------------------
__global__ void l2norm128(float* __restrict__ X) {
    size_t row = blockIdx.x;
    float* p = X + row * KD;
    int t = threadIdx.x;                      // 128
    float v = p[t];
    float sq = v * v;
    #pragma unroll
    for (int o = 16; o; o >>= 1) sq += __shfl_xor_sync(0xffffffffu, sq, o);
    __shared__ float ws[4];
    if ((t & 31) == 0) ws[t >> 5] = sq;
    __syncthreads();
    float tot = ws[0] + ws[1] + ws[2] + ws[3];
    p[t] = v * (1.0f / fmaxf(sqrtf(tot), 1e-12f));
}

__global__ void rowsum(const float* __restrict__ X, float* __restrict__ l, int cols) {
    size_t row = blockIdx.x;
    const float* p = X + row * (size_t)cols;
    int t = threadIdx.x;                      // 256
    float s = 0.f;
    for (int j = t; j < cols; j += 256) s += p[j];
    #pragma unroll
    for (int o = 16; o; o >>= 1) s += __shfl_xor_sync(0xffffffffu, s, o);
    __shared__ float ws[8];
    if ((t & 31) == 0) ws[t >> 5] = s;
    __syncthreads();
    if (t == 0) {
        float tot = 0.f;
        #pragma unroll
        for (int w = 0; w < 8; w++) tot += ws[w];
        l[row] = tot;
    }
}

// ---------------- InstanceNorm ----------------------------------------------
__global__ void inst_stats(const float* __restrict__ X, float* __restrict__ mu,
                           float* __restrict__ rstd) {
    int s = blockIdx.x >> 8;
    int c = blockIdx.x & 255;
    const float* p = X + (size_t)s * LQ * CDIM + c;
    int t = threadIdx.x;                      // 256
    __shared__ float red[256];
    float sum = 0.f;
    for (int q = t; q < LQ; q += 256) sum += p[(size_t)q * CDIM];
    red[t] = sum;
    __syncthreads();
    for (int st = 128; st > 0; st >>= 1) {
        if (t < st) red[t] += red[t + st];
        __syncthreads();
    }
    float m = red[0] / (float)LQ;
    __syncthreads();
    float vs = 0.f;
    for (int q = t; q < LQ; q += 256) {
        float d = p[(size_t)q * CDIM] - m;
        vs += d * d;
    }
    red[t] = vs;
    __syncthreads();
    for (int st = 128; st > 0; st >>= 1) {
        if (t < st) red[t] += red[t + st];
        __syncthreads();
    }
    if (t == 0) {
        mu[blockIdx.x] = m;
        rstd[blockIdx.x] = rsqrtf(red[0] / (float)LQ + 1e-5f);
    }
}

__global__ void inst_apply(float* __restrict__ X, const float* __restrict__ mu,
                           const float* __restrict__ rstd) {
    int i = blockIdx.x * 256 + threadIdx.x;
    int c = i & (CDIM - 1);
    int s = i / (LQ * CDIM);
    int idx = s * CDIM + c;
    X[i] = (X[i] - mu[idx]) * rstd[idx];
}

// ---------------- small 16x16 projection (cross V) ---------------------------
__global__ void proj16(const float* __restrict__ X, const float* __restrict__ W,
                       const float* __restrict__ b, float* __restrict__ Y, int rows) {
    __shared__ float Ws[16][16];
    __shared__ float bs[16];
    int t = threadIdx.x;                      // 256
    Ws[t >> 4][t & 15] = W[t];
    if (t < 16) bs[t] = b[t];
    __syncthreads();
    int r = blockIdx.x * 256 + t;
    if (r >= rows) return;
    const float* px = X + (size_t)r * CE;
    float x[16];
    #pragma unroll
    for (int i = 0; i < 16; i++) x[i] = px[i];
    float* py = Y + (size_t)r * CE;
    #pragma unroll
    for (int o = 0; o < 16; o++) {
        float acc = bs[o];
        #pragma unroll
        for (int i = 0; i < 16; i++) acc += x[i] * Ws[o][i];
        py[o] = acc;
    }
}

// ---------------- fused cross flash attention --------------------------------
// block: 128 queries x (split of key tiles of 64). dv = 16.
// smem: Qs[128][132] | Ks[64][132] (region reused as Ps[128][68]) | Vs[64][16]
#define FSM_K  16896
#define FSM_V  25600                 // FSM_V - FSM_K = 8704 = 128*68 (Ps fits)
#define FSM_FLOATS (FSM_V + 64 * 16)
#define FSM_BYTES  (FSM_FLOATS * 4)

__global__ void __launch_bounds__(256) flash_cross(
    const float* __restrict__ Wq, const float* __restrict__ Wk,
    const float* __restrict__ Vv, float* __restrict__ PO, float* __restrict__ PL) {
    extern __shared__ float sm[];
    float* Qs = sm;             // [128][132]
    float* Ks = sm + FSM_K;     // [64][132], reused as Ps[128][68]
    float* Vs = sm + FSM_V;     // [64][16]

    const int t  = threadIdx.x;
    const int tx = t & 15, ty = t >> 4;
    const int q0 = blockIdx.x * 128;
    const int s  = blockIdx.y;
    const int sp = blockIdx.z;

    const float* wq = Wq + ((size_t)s * LQ + q0) * KD;
    const float* wk = Wk + (size_t)s * LK * KD;
    const float* wv = Vv + (size_t)s * LK * CE;

    // load Q tile (128 x 128)
    {
        int c4 = (t & 31) * 4;
        for (int r = t >> 5; r < 128; r += 8)
            *(float4*)&Qs[r * 132 + c4] = *(const float4*)&wq[(size_t)r * KD + c4];
    }

    const int t_lo = sp * KTILES / NSPLIT;
    const int t_hi = (sp + 1) * KTILES / NSPLIT;

    float oacc[8] = {0.f, 0.f, 0.f, 0.f, 0.f, 0.f, 0.f, 0.f};
    float lacc[8] = {0.f, 0.f, 0.f, 0.f, 0.f, 0.f, 0.f, 0.f};
    const int qv = t >> 1, dh = (t & 1) * 8;

    for (int kt = t_lo; kt < t_hi; kt++) {
        __syncthreads();                      // prev Ps/Vs consumed
        {
            int c4 = (t & 31) * 4;
            const float* src = wk + (size_t)(kt * 64) * KD;
            for (int r = t >> 5; r < 64; r += 8)
                *(float4*)&Ks[r * 132 + c4] = *(const float4*)&src[(size_t)r * KD + c4];
            int vr = t >> 2, vc = (t & 3) * 4;
            *(float4*)&Vs[vr * 16 + vc] =
                *(const float4*)&wv[(size_t)(kt * 64 + vr) * CE + vc];
        }
        __syncthreads();

        // scores: 128x64, K=128, f32x2 packed
        unsigned long long acc[8][4];
        #pragma unroll
        for (int i = 0; i < 8; i++)
            #pragma unroll
            for (int j = 0; j < 4; j++) acc[i][j] = 0ull;
        #pragma unroll 4
        for (int kc = 0; kc < 128; kc += 4) {
            float4 av[8], bv[4];
            #pragma unroll
            for (int i = 0; i < 8; i++) av[i] = *(float4*)&Qs[(ty + 16 * i) * 132 + kc];
            #pragma unroll
            for (int j = 0; j < 4; j++) bv[j] = *(float4*)&Ks[(tx + 16 * j) * 132 + kc];
            unsigned long long b01[4], b23[4];
            #pragma unroll
            for (int j = 0; j < 4; j++) {
                b01[j] = pk(bv[j].x, bv[j].y);
                b23[j] = pk(bv[j].z, bv[j].w);
            }
            #pragma unroll
            for (int i = 0; i < 8; i++) {
                unsigned long long a01 = pk(av[i].x, av[i].y);
                unsigned long long a23 = pk(av[i].z, av[i].w);
                #pragma unroll
                for (int j = 0; j < 4; j++) {
                    fma2(acc[i][j], a01, b01[j]);
                    fma2(acc[i][j], a23, b23[j]);
                }
            }
        }

        float p[8][4];
        #pragma unroll
        for (int i = 0; i < 8; i++)
            #pragma unroll
            for (int j = 0; j < 4; j++) {
                float e = __expf(30.0f * unpk_sum(acc[i][j]));
                p[i][j] = e;
                lacc[i] += e;
            }
        __syncthreads();                      // all done reading Ks
        #pragma unroll
        for (int i = 0; i < 8; i++)
            #pragma unroll
            for (int j = 0; j < 4; j++)
                Ks[(ty + 16 * i) * 68 + tx + 16 * j] = p[i][j];   // Ps alias
        __syncthreads();

        // PV: o[q][dh..dh+7] += sum_k Ps[q][k] * Vs[k][dh..]
        const float* Pr = Ks + qv * 68;
        #pragma unroll 8
        for (int kk = 0; kk < 64; kk++) {
            float w = Pr[kk];
            float4 v0 = *(float4*)&Vs[kk * 16 + dh];
            float4 v1 = *(float4*)&Vs[kk * 16 + dh + 4];
            oacc[0] += w * v0.x; oacc[1] += w * v0.y;
            oacc[2] += w * v0.z; oacc[3] += w * v0.w;
            oacc[4] += w * v1.x; oacc[5] += w * v1.y;
            oacc[6] += w * v1.z; oacc[7] += w * v1.w;
        }
    }

    // reduce row sums across tx (lane bits 0..3) and write partials
    #pragma unroll
    for (int i = 0; i < 8; i++) {
        float v = lacc[i];
        v += __shfl_xor_sync(0xffffffffu, v, 1);
        v += __shfl_xor_sync(0xffffffffu, v, 2);
        v += __shfl_xor_sync(0xffffffffu, v, 4);
        v += __shfl_xor_sync(0xffffffffu, v, 8);
        if (tx == 0)
            PL[(size_t)(s * NSPLIT + sp) * LQ + q0 + ty + 16 * i] = v;
    }
    float* po = PO + ((size_t)(s * NSPLIT + sp) * LQ + q0 + qv) * CE + dh;
    *(float4*)&po[0] = make_float4(oacc[0], oacc[1], oacc[2], oacc[3]);
    *(float4*)&po[4] = make_float4(oacc[4], oacc[5], oacc[6], oacc[7]);
}

// ---------------- split combine + output layout ------------------------------
__global__ void combine_out(const float* __restrict__ PO, const float* __restrict__ PL,
                            float* __restrict__ out) {
    int i = blockIdx.x * 256 + threadIdx.x;    // over S2*CE*HW
    int p = i % HW;
    int d = (i / HW) % CE;
    int s = i / (CE * HW);
    float so = 0.f, sl = 0.f;
    #pragma unroll
    for (int sp = 0; sp < NSPLIT; sp++) {
        so += PO[((size_t)(s * NSPLIT + sp) * LQ + p) * CE + d];
        sl += PL[(size_t)(s * NSPLIT + sp) * LQ + p];
    }
    out[i] = so / sl;
}

// ---------------- host orchestration -----------------------------------------
extern "C" void kernel_launch(void* const* d_in, const int* in_sizes, int n_in,
                              void* d_out, int out_size) {
    const float* tgt   = (const float*)d_in[0];
    const float* mem   = (const float*)d_in[1];
    const float* pos   = (const float*)d_in[2];
    const float* WKs_w = (const float*)d_in[3];
    const float* WKs_b = (const float*)d_in[4];
    const float* WVs_w = (const float*)d_in[5];
    const float* WVs_b = (const float*)d_in[6];
    const float* WKc_w = (const float*)d_in[7];
    const float* WKc_b = (const float*)d_in[8];
    const float* WVc_w = (const float*)d_in[9];
    const float* WVc_b = (const float*)d_in[10];
    float* out = (float*)d_out;

    float *tgtT, *memT, *posT, *wqs, *wvs, *wvsT, *Ss, *lself, *x, *mu, *rstd;
    float *wqc, *wkc, *wvc, *po, *pl;
    cudaGetSymbolAddress((void**)&tgtT,  g_tgtT);
    cudaGetSymbolAddress((void**)&memT,  g_memT);
    cudaGetSymbolAddress((void**)&posT,  g_posT);
    cudaGetSymbolAddress((void**)&wqs,   g_wqs);
    cudaGetSymbolAddress((void**)&wvs,   g_wvs);
    cudaGetSymbolAddress((void**)&wvsT,  g_wvsT);
    cudaGetSymbolAddress((void**)&Ss,    g_Ss);
    cudaGetSymbolAddress((void**)&lself, g_lself);
    cudaGetSymbolAddress((void**)&x,     g_x);
    cudaGetSymbolAddress((void**)&mu,    g_mu);
    cudaGetSymbolAddress((void**)&rstd,  g_rstd);
    cudaGetSymbolAddress((void**)&wqc,   g_wqc);
    cudaGetSymbolAddress((void**)&wkc,   g_wkc);
    cudaGetSymbolAddress((void**)&wvc,   g_wvc);
    cudaGetSymbolAddress((void**)&po,    g_po);
    cudaGetSymbolAddress((void**)&pl,    g_pl);

    // no static guard (harness rule): idempotent, called every launch
    cudaFuncSetAttribute(flash_cross,
                         cudaFuncAttributeMaxDynamicSharedMemorySize, FSM_BYTES);

    dim3 tb(32, 8);
    // layout transposes: [C][HW] -> [HW][C]
    transpose_k<<<dim3(HW / 32, CDIM / 32, S2), tb>>>(
        tgt, tgtT, CDIM, HW, (size_t)CDIM * HW, (size_t)HW * CDIM, 0, S2);
    transpose_k<<<dim3(HW / 32, CDIM / 32, NF * S2), tb>>>(
        mem, memT, CDIM, HW, (size_t)CDIM * HW, (size_t)LK * CDIM,
        (size_t)HW * CDIM, S2);
    transpose_k<<<dim3(HW / 32, 1, NF * S2), tb>>>(
        pos, posT, CE, HW, (size_t)CE * HW, (size_t)LK * CE, (size_t)HW * CE, S2);

    // self projections
    gemm_nt<<<dim3(KD / 64, LQ / 128, S2), 256>>>(
        tgtT, WKs_w, WKs_b, nullptr, nullptr, wqs, LQ, KD, CDIM, 0,
        (size_t)LQ * CDIM, 0, (size_t)LQ * KD, 0, 0);
    l2norm128<<<S2 * LQ, 128>>>(wqs);
    gemm_nt<<<dim3(CDIM / 64, LQ / 128, S2), 256>>>(
        tgtT, WVs_w, WVs_b, nullptr, nullptr, wvs, LQ, CDIM, CDIM, 0,
        (size_t)LQ * CDIM, 0, (size_t)LQ * CDIM, 0, 0);
    transpose_k<<<dim3(CDIM / 32, LQ / 32, S2), tb>>>(
        wvs, wvsT, LQ, CDIM, (size_t)LQ * CDIM, (size_t)CDIM * LQ, 0, S2);

    // self attention: exp-scores -> row sums -> PV (/l + residual)
    gemm_nt<<<dim3(LQ / 64, LQ / 128, S2), 256>>>(
        wqs, wqs, nullptr, nullptr, nullptr, Ss, LQ, LQ, KD, 1,
        (size_t)LQ * KD, (size_t)LQ * KD, (size_t)LQ * LQ, 0, 0);
    rowsum<<<S2 * LQ, 256>>>(Ss, lself, LQ);
    gemm_nt<<<dim3(CDIM / 64, LQ / 128, S2), 256>>>(
        Ss, wvsT, nullptr, tgtT, lself, x, LQ, CDIM, LQ, 0,
        (size_t)LQ * LQ, (size_t)CDIM * LQ, (size_t)LQ * CDIM,
        (size_t)LQ * CDIM, (size_t)LQ);

    // InstanceNorm
    inst_stats<<<S2 * CDIM, 256>>>(x, mu, rstd);
    inst_apply<<<(S2 * LQ * CDIM) / 256, 256>>>(x, mu, rstd);

    // cross projections
    gemm_nt<<<dim3(KD / 64, LQ / 128, S2), 256>>>(
        x, WKc_w, WKc_b, nullptr, nullptr, wqc, LQ, KD, CDIM, 0,
        (size_t)LQ * CDIM, 0, (size_t)LQ * KD, 0, 0);
    l2norm128<<<S2 * LQ, 128>>>(wqc);
    gemm_nt<<<dim3(KD / 64, LK / 128, S2), 256>>>(
        memT, WKc_w, WKc_b, nullptr, nullptr, wkc, LK, KD, CDIM, 0,
        (size_t)LK * CDIM, 0, (size_t)LK * KD, 0, 0);
    l2norm128<<<S2 * LK, 128>>>(wkc);
    proj16<<<(S2 * LK) / 256, 256>>>(posT, WVc_w, WVc_b, wvc, S2 * LK);

    // fused cross attention (split-KV) + combine into final layout
    flash_cross<<<dim3(LQ / 128, S2, NSPLIT), 256, FSM_BYTES>>>(wqc, wkc, wvc, po, pl);
    combine_out<<<(S2 * CE * HW) / 256, 256>>>(po, pl, out);
}

// round 14
// speedup vs baseline: 1.0040x; 1.0040x over previous
#include <cuda_runtime.h>
#include <math.h>

// Problem constants
#define S2      2
#define CDIM    256
#define KD      128
#define CE      16
#define NF      5
#define HW      2304               // 48*48
#define LQ      2304
#define LK      11520              // 5*2304
#define NSPLIT  8
#define KTILES  (LK / 64)          // 180 key tiles of 64

// ---------------- scratch (static device memory; no cudaMalloc allowed) ----
__device__ float g_tgtT[S2 * LQ * CDIM];
__device__ float g_memT[S2 * LK * CDIM];
__device__ float g_posT[S2 * LK * CE];
__device__ float g_wqs [S2 * LQ * KD];
__device__ float g_wvs [S2 * LQ * CDIM];
__device__ float g_wvsT[S2 * CDIM * LQ];
__device__ float g_Ss  [(size_t)S2 * LQ * LQ];   // self exp-scores (~42MB)
__device__ float g_lself[S2 * LQ];
__device__ float g_x   [S2 * LQ * CDIM];
__device__ float g_mu  [S2 * CDIM];
__device__ float g_rstd[S2 * CDIM];
__device__ float g_wqc [S2 * LQ * KD];
__device__ float g_wkc [S2 * LK * KD];
__device__ float g_wvc [S2 * LK * CE];
__device__ float g_po  [S2 * NSPLIT * LQ * CE];  // cross partial outputs (unnormalized)
__device__ float g_pl  [S2 * NSPLIT * LQ];       // cross partial row sums

// ---------------- f32x2 packed FMA helpers ----------------------------------
union F2u { float2 f; unsigned long long u; };

__device__ __forceinline__ void fma2(unsigned long long& acc,
                                     unsigned long long a, unsigned long long b) {
    asm("fma.rn.f32x2 %0, %1, %2, %0;" : "+l"(acc) : "l"(a), "l"(b));
}
__device__ __forceinline__ float unpk_sum(unsigned long long v) {
    F2u t; t.u = v; return t.f.x + t.f.y;
}

// ---------------- tiled transpose: in [R][Cc] -> out [Cc][R], batched --------
__global__ void transpose_k(const float* __restrict__ in, float* __restrict__ out,
                            int R, int Cc, size_t inZ, size_t outS, size_t outF,
                            int mods) {
    __shared__ float tile[32][33];
    int z = blockIdx.z;
    in  += (size_t)z * inZ;
    out += (size_t)(z % mods) * outS + (size_t)(z / mods) * outF;
    int c0 = blockIdx.x * 32;
    int r0 = blockIdx.y * 32;
    int tx = threadIdx.x, ty = threadIdx.y;          // 32 x 8
    #pragma unroll
    for (int i = ty; i < 32; i += 8) {
        int r = r0 + i, c = c0 + tx;
        if (r < R && c < Cc) tile[i][tx] = in[(size_t)r * Cc + c];
    }
    __syncthreads();
    #pragma unroll
    for (int i = ty; i < 32; i += 8) {
        int c = c0 + i, r = r0 + tx;
        if (r < R && c < Cc) out[(size_t)c * R + r] = tile[tx][i];
    }
}

// ---------------- GEMM: C[M,N] = A[M,K]*B[N,K]^T with fused epilogues --------
// 128x64 tile, 256 threads, 8x4 micro (strided), f32x2 packed along K.
// smem rows read as ulonglong2 (two pre-packed f32x2 operands, no MOVs).
// epilogue: (+bias[col]) -> (exp(30x)) -> (/rowdiv[row]) -> (+resid[row][col])
__global__ void __launch_bounds__(256, 2) gemm_nt(
    const float* __restrict__ A, const float* __restrict__ B,
    const float* __restrict__ bias, const float* __restrict__ resid,
    const float* __restrict__ rowdiv, float* __restrict__ C,
    int M, int N, int K, int do_exp,
    size_t sA, size_t sB, size_t sC, size_t sR, size_t sD) {
    int z = blockIdx.z;
    A += (size_t)z * sA;
    B += (size_t)z * sB;
    C += (size_t)z * sC;
    if (resid)  resid  += (size_t)z * sR;
    if (rowdiv) rowdiv += (size_t)z * sD;

    __shared__ float As[128][36];   // 32 K-floats + 4 pad (odd quads -> conflict-free)
    __shared__ float Bs[64][36];

    const int t  = threadIdx.x;
    const int tx = t & 15, ty = t >> 4;
    const int row0 = blockIdx.y * 128, col0 = blockIdx.x * 64;
    const int c8 = (t & 7) * 4, rr = t >> 3;

    unsigned long long acc[8][4];
    #pragma unroll
    for (int i = 0; i < 8; i++)
        #pragma unroll
        for (int j = 0; j < 4; j++) acc[i][j] = 0ull;

    for (int k0 = 0; k0 < K; k0 += 32) {
        #pragma unroll
        for (int r = rr; r < 128; r += 32)
            *(float4*)&As[r][c8] = *(const float4*)&A[(size_t)(row0 + r) * K + k0 + c8];
        #pragma unroll
        for (int r = rr; r < 64; r += 32)
            *(float4*)&Bs[r][c8] = *(const float4*)&B[(size_t)(col0 + r) * K + k0 + c8];
        __syncthreads();
        #pragma unroll
        for (int kc = 0; kc < 32; kc += 4) {
            ulonglong2 a[8], b[4];
            #pragma unroll
            for (int i = 0; i < 8; i++)
                a[i] = *(const ulonglong2*)&As[ty + 16 * i][kc];
            #pragma unroll
            for (int j = 0; j < 4; j++)
                b[j] = *(const ulonglong2*)&Bs[tx + 16 * j][kc];
            #pragma unroll
            for (int i = 0; i < 8; i++)
                #pragma unroll
                for (int j = 0; j < 4; j++) {
                    fma2(acc[i][j], a[i].x, b[j].x);
                    fma2(acc[i][j], a[i].y, b[j].y);
                }
        }
        __syncthreads();
    }

    #pragma unroll
    for (int i = 0; i < 8; i++) {
        int r = row0 + ty + 16 * i;
        float inv = rowdiv ? (1.0f / rowdiv[r]) : 1.0f;
        #pragma unroll
        for (int j = 0; j < 4; j++) {
            int c = col0 + tx + 16 * j;
            float v = unpk_sum(acc[i][j]);
            if (bias) v += bias[c];
            if (do_exp) v = __expf(30.0f * v);
            v *= inv;
            if (resid) v += resid[(size_t)r * N + c];
            C[(size_t)r * N + c] = v;
        }
    }
}

// ---------------- row ops ----------------------------------------------------
__global__ void l2norm128(float* __restrict__ X) {
    size_t row = blockIdx.x;
    float* p = X + row * KD;
    int t = threadIdx.x;                      // 128
    float v = p[t];
    float sq = v * v;
    #pragma unroll
    for (int o = 16; o; o >>= 1) sq += __shfl_xor_sync(0xffffffffu, sq, o);
    __shared__ float ws[4];
    if ((t & 31) == 0) ws[t >> 5] = sq;
    __syncthreads();
    float tot = ws[0] + ws[1] + ws[2] + ws[3];
    p[t] = v * (1.0f / fmaxf(sqrtf(tot), 1e-12f));
}

__global__ void rowsum(const float* __restrict__ X, float* __restrict__ l, int cols) {
    size_t row = blockIdx.x;
    const float* p = X + row * (size_t)cols;
    int t = threadIdx.x;                      // 256
    float s = 0.f;
    for (int j = t; j < cols; j += 256) s += p[j];
    #pragma unroll
    for (int o = 16; o; o >>= 1) s += __shfl_xor_sync(0xffffffffu, s, o);
    __shared__ float ws[8];
    if ((t & 31) == 0) ws[t >> 5] = s;
    __syncthreads();
    if (t == 0) {
        float tot = 0.f;
        #pragma unroll
        for (int w = 0; w < 8; w++) tot += ws[w];
        l[row] = tot;
    }
}

// ---------------- InstanceNorm ----------------------------------------------
__global__ void inst_stats(const float* __restrict__ X, float* __restrict__ mu,
                           float* __restrict__ rstd) {
    int s = blockIdx.x >> 8;
    int c = blockIdx.x & 255;
    const float* p = X + (size_t)s * LQ * CDIM + c;
    int t = threadIdx.x;                      // 256
    __shared__ float red[256];
    float sum = 0.f;
    for (int q = t; q < LQ; q += 256) sum += p[(size_t)q * CDIM];
    red[t] = sum;
    __syncthreads();
    for (int st = 128; st > 0; st >>= 1) {
        if (t < st) red[t] += red[t + st];
        __syncthreads();
    }
    float m = red[0] / (float)LQ;
    __syncthreads();
    float vs = 0.f;
    for (int q = t; q < LQ; q += 256) {
        float d = p[(size_t)q * CDIM] - m;
        vs += d * d;
    }
    red[t] = vs;
    __syncthreads();
    for (int st = 128; st > 0; st >>= 1) {
        if (t < st) red[t] += red[t + st];
        __syncthreads();
    }
    if (t == 0) {
        mu[blockIdx.x] = m;
        rstd[blockIdx.x] = rsqrtf(red[0] / (float)LQ + 1e-5f);
    }
}

__global__ void inst_apply(float* __restrict__ X, const float* __restrict__ mu,
                           const float* __restrict__ rstd) {
    int i = blockIdx.x * 256 + threadIdx.x;
    int c = i & (CDIM - 1);
    int s = i / (LQ * CDIM);
    int idx = s * CDIM + c;
    X[i] = (X[i] - mu[idx]) * rstd[idx];
}

// ---------------- small 16x16 projection (cross V) ---------------------------
__global__ void proj16(const float* __restrict__ X, const float* __restrict__ W,
                       const float* __restrict__ b, float* __restrict__ Y, int rows) {
    __shared__ float Ws[16][16];
    __shared__ float bs[16];
    int t = threadIdx.x;                      // 256
    Ws[t >> 4][t & 15] = W[t];
    if (t < 16) bs[t] = b[t];
    __syncthreads();
    int r = blockIdx.x * 256 + t;
    if (r >= rows) return;
    const float* px = X + (size_t)r * CE;
    float x[16];
    #pragma unroll
    for (int i = 0; i < 16; i++) x[i] = px[i];
    float* py = Y + (size_t)r * CE;
    #pragma unroll
    for (int o = 0; o < 16; o++) {
        float acc = bs[o];
        #pragma unroll
        for (int i = 0; i < 16; i++) acc += x[i] * Ws[o][i];
        py[o] = acc;
    }
}

// ---------------- fused cross flash attention --------------------------------
// block: 128 queries x (split of key tiles of 64). dv = 16.
// smem: Qs[128][132] | Ks[64][132] (region reused as Ps[128][68]) | Vs[64][16]
#define FSM_K  16896
#define FSM_V  25600                 // FSM_V - FSM_K = 8704 = 128*68 (Ps fits)
#define FSM_FLOATS (FSM_V + 64 * 16)
#define FSM_BYTES  (FSM_FLOATS * 4)

__global__ void __launch_bounds__(256) flash_cross(
    const float* __restrict__ Wq, const float* __restrict__ Wk,
    const float* __restrict__ Vv, float* __restrict__ PO, float* __restrict__ PL) {
    extern __shared__ float sm[];
    float* Qs = sm;             // [128][132]
    float* Ks = sm + FSM_K;     // [64][132], reused as Ps[128][68]
    float* Vs = sm + FSM_V;     // [64][16]

    const int t  = threadIdx.x;
    const int tx = t & 15, ty = t >> 4;
    const int q0 = blockIdx.x * 128;
    const int s  = blockIdx.y;
    const int sp = blockIdx.z;

    const float* wq = Wq + ((size_t)s * LQ + q0) * KD;
    const float* wk = Wk + (size_t)s * LK * KD;
    const float* wv = Vv + (size_t)s * LK * CE;

    // load Q tile (128 x 128)
    {
        int c4 = (t & 31) * 4;
        for (int r = t >> 5; r < 128; r += 8)
            *(float4*)&Qs[r * 132 + c4] = *(const float4*)&wq[(size_t)r * KD + c4];
    }

    const int t_lo = sp * KTILES / NSPLIT;
    const int t_hi = (sp + 1) * KTILES / NSPLIT;

    float oacc[8] = {0.f, 0.f, 0.f, 0.f, 0.f, 0.f, 0.f, 0.f};
    float lacc[8] = {0.f, 0.f, 0.f, 0.f, 0.f, 0.f, 0.f, 0.f};
    const int qv = t >> 1, dh = (t & 1) * 8;

    for (int kt = t_lo; kt < t_hi; kt++) {
        __syncthreads();                      // prev Ps/Vs consumed
        {
            int c4 = (t & 31) * 4;
            const float* src = wk + (size_t)(kt * 64) * KD;
            for (int r = t >> 5; r < 64; r += 8)
                *(float4*)&Ks[r * 132 + c4] = *(const float4*)&src[(size_t)r * KD + c4];
            int vr = t >> 2, vc = (t & 3) * 4;
            *(float4*)&Vs[vr * 16 + vc] =
                *(const float4*)&wv[(size_t)(kt * 64 + vr) * CE + vc];
        }
        __syncthreads();

        // scores: 128x64, K=128, f32x2 packed via direct ulonglong2 smem reads
        unsigned long long acc[8][4];
        #pragma unroll
        for (int i = 0; i < 8; i++)
            #pragma unroll
            for (int j = 0; j < 4; j++) acc[i][j] = 0ull;
        #pragma unroll 4
        for (int kc = 0; kc < 128; kc += 4) {
            ulonglong2 a[8], b[4];
            #pragma unroll
            for (int i = 0; i < 8; i++)
                a[i] = *(const ulonglong2*)&Qs[(ty + 16 * i) * 132 + kc];
            #pragma unroll
            for (int j = 0; j < 4; j++)
                b[j] = *(const ulonglong2*)&Ks[(tx + 16 * j) * 132 + kc];
            #pragma unroll
            for (int i = 0; i < 8; i++)
                #pragma unroll
                for (int j = 0; j < 4; j++) {
                    fma2(acc[i][j], a[i].x, b[j].x);
                    fma2(acc[i][j], a[i].y, b[j].y);
                }
        }

        float p[8][4];
        #pragma unroll
        for (int i = 0; i < 8; i++)
            #pragma unroll
            for (int j = 0; j < 4; j++) {
                float e = __expf(30.0f * unpk_sum(acc[i][j]));
                p[i][j] = e;
                lacc[i] += e;
            }
        __syncthreads();                      // all done reading Ks
        #pragma unroll
        for (int i = 0; i < 8; i++)
            #pragma unroll
            for (int j = 0; j < 4; j++)
                Ks[(ty + 16 * i) * 68 + tx + 16 * j] = p[i][j];   // Ps alias
        __syncthreads();

        // PV: o[q][dh..dh+7] += sum_k Ps[q][k] * Vs[k][dh..]
        const float* Pr = Ks + qv * 68;
        #pragma unroll 8
        for (int kk = 0; kk < 64; kk++) {
            float w = Pr[kk];
            float4 v0 = *(float4*)&Vs[kk * 16 + dh];
            float4 v1 = *(float4*)&Vs[kk * 16 + dh + 4];
            oacc[0] += w * v0.x; oacc[1] += w * v0.y;
            oacc[2] += w * v0.z; oacc[3] += w * v0.w;
            oacc[4] += w * v1.x; oacc[5] += w * v1.y;
            oacc[6] += w * v1.z; oacc[7] += w * v1.w;
        }
    }

    // reduce row sums across tx (lane bits 0..3) and write partials
    #pragma unroll
    for (int i = 0; i < 8; i++) {
        float v = lacc[i];
        v += __shfl_xor_sync(0xffffffffu, v, 1);
        v += __shfl_xor_sync(0xffffffffu, v, 2);
        v += __shfl_xor_sync(0xffffffffu, v, 4);
        v += __shfl_xor_sync(0xffffffffu, v, 8);
        if (tx == 0)
            PL[(size_t)(s * NSPLIT + sp) * LQ + q0 + ty + 16 * i] = v;
    }
    float* po = PO + ((size_t)(s * NSPLIT + sp) * LQ + q0 + qv) * CE + dh;
    *(float4*)&po[0] = make_float4(oacc[0], oacc[1], oacc[2], oacc[3]);
    *(float4*)&po[4] = make_float4(oacc[4], oacc[5], oacc[6], oacc[7]);
}

// ---------------- split combine + output layout ------------------------------
__global__ void combine_out(const float* __restrict__ PO, const float* __restrict__ PL,
                            float* __restrict__ out) {
    int i = blockIdx.x * 256 + threadIdx.x;    // over S2*CE*HW
    int p = i % HW;
    int d = (i / HW) % CE;
    int s = i / (CE * HW);
    float so = 0.f, sl = 0.f;
    #pragma unroll
    for (int sp = 0; sp < NSPLIT; sp++) {
        so += PO[((size_t)(s * NSPLIT + sp) * LQ + p) * CE + d];
        sl += PL[(size_t)(s * NSPLIT + sp) * LQ + p];
    }
    out[i] = so / sl;
}

// ---------------- host orchestration -----------------------------------------
extern "C" void kernel_launch(void* const* d_in, const int* in_sizes, int n_in,
                              void* d_out, int out_size) {
    const float* tgt   = (const float*)d_in[0];
    const float* mem   = (const float*)d_in[1];
    const float* pos   = (const float*)d_in[2];
    const float* WKs_w = (const float*)d_in[3];
    const float* WKs_b = (const float*)d_in[4];
    const float* WVs_w = (const float*)d_in[5];
    const float* WVs_b = (const float*)d_in[6];
    const float* WKc_w = (const float*)d_in[7];
    const float* WKc_b = (const float*)d_in[8];
    const float* WVc_w = (const float*)d_in[9];
    const float* WVc_b = (const float*)d_in[10];
    float* out = (float*)d_out;

    float *tgtT, *memT, *posT, *wqs, *wvs, *wvsT, *Ss, *lself, *x, *mu, *rstd;
    float *wqc, *wkc, *wvc, *po, *pl;
    cudaGetSymbolAddress((void**)&tgtT,  g_tgtT);
    cudaGetSymbolAddress((void**)&memT,  g_memT);
    cudaGetSymbolAddress((void**)&posT,  g_posT);
    cudaGetSymbolAddress((void**)&wqs,   g_wqs);
    cudaGetSymbolAddress((void**)&wvs,   g_wvs);
    cudaGetSymbolAddress((void**)&wvsT,  g_wvsT);
    cudaGetSymbolAddress((void**)&Ss,    g_Ss);
    cudaGetSymbolAddress((void**)&lself, g_lself);
    cudaGetSymbolAddress((void**)&x,     g_x);
    cudaGetSymbolAddress((void**)&mu,    g_mu);
    cudaGetSymbolAddress((void**)&rstd,  g_rstd);
    cudaGetSymbolAddress((void**)&wqc,   g_wqc);
    cudaGetSymbolAddress((void**)&wkc,   g_wkc);
    cudaGetSymbolAddress((void**)&wvc,   g_wvc);
    cudaGetSymbolAddress((void**)&po,    g_po);
    cudaGetSymbolAddress((void**)&pl,    g_pl);

    // no static guard (harness rule): idempotent, called every launch
    cudaFuncSetAttribute(flash_cross,
                         cudaFuncAttributeMaxDynamicSharedMemorySize, FSM_BYTES);

    dim3 tb(32, 8);
    // layout transposes: [C][HW] -> [HW][C]
    transpose_k<<<dim3(HW / 32, CDIM / 32, S2), tb>>>(
        tgt, tgtT, CDIM, HW, (size_t)CDIM * HW, (size_t)HW * CDIM, 0, S2);
    transpose_k<<<dim3(HW / 32, CDIM / 32, NF * S2), tb>>>(
        mem, memT, CDIM, HW, (size_t)CDIM * HW, (size_t)LK * CDIM,
        (size_t)HW * CDIM, S2);
    transpose_k<<<dim3(HW / 32, 1, NF * S2), tb>>>(
        pos, posT, CE, HW, (size_t)CE * HW, (size_t)LK * CE, (size_t)HW * CE, S2);

    // self projections
    gemm_nt<<<dim3(KD / 64, LQ / 128, S2), 256>>>(
        tgtT, WKs_w, WKs_b, nullptr, nullptr, wqs, LQ, KD, CDIM, 0,
        (size_t)LQ * CDIM, 0, (size_t)LQ * KD, 0, 0);
    l2norm128<<<S2 * LQ, 128>>>(wqs);
    gemm_nt<<<dim3(CDIM / 64, LQ / 128, S2), 256>>>(
        tgtT, WVs_w, WVs_b, nullptr, nullptr, wvs, LQ, CDIM, CDIM, 0,
        (size_t)LQ * CDIM, 0, (size_t)LQ * CDIM, 0, 0);
    transpose_k<<<dim3(CDIM / 32, LQ / 32, S2), tb>>>(
        wvs, wvsT, LQ, CDIM, (size_t)LQ * CDIM, (size_t)CDIM * LQ, 0, S2);

    // self attention: exp-scores -> row sums -> PV (/l + residual)
    gemm_nt<<<dim3(LQ / 64, LQ / 128, S2), 256>>>(
        wqs, wqs, nullptr, nullptr, nullptr, Ss, LQ, LQ, KD, 1,
        (size_t)LQ * KD, (size_t)LQ * KD, (size_t)LQ * LQ, 0, 0);
    rowsum<<<S2 * LQ, 256>>>(Ss, lself, LQ);
    gemm_nt<<<dim3(CDIM / 64, LQ / 128, S2), 256>>>(
        Ss, wvsT, nullptr, tgtT, lself, x, LQ, CDIM, LQ, 0,
        (size_t)LQ * LQ, (size_t)CDIM * LQ, (size_t)LQ * CDIM,
        (size_t)LQ * CDIM, (size_t)LQ);

    // InstanceNorm
    inst_stats<<<S2 * CDIM, 256>>>(x, mu, rstd);
    inst_apply<<<(S2 * LQ * CDIM) / 256, 256>>>(x, mu, rstd);

    // cross projections
    gemm_nt<<<dim3(KD / 64, LQ / 128, S2), 256>>>(
        x, WKc_w, WKc_b, nullptr, nullptr, wqc, LQ, KD, CDIM, 0,
        (size_t)LQ * CDIM, 0, (size_t)LQ * KD, 0, 0);
    l2norm128<<<S2 * LQ, 128>>>(wqc);
    gemm_nt<<<dim3(KD / 64, LK / 128, S2), 256>>>(
        memT, WKc_w, WKc_b, nullptr, nullptr, wkc, LK, KD, CDIM, 0,
        (size_t)LK * CDIM, 0, (size_t)LK * KD, 0, 0);
    l2norm128<<<S2 * LK, 128>>>(wkc);
    proj16<<<(S2 * LK) / 256, 256>>>(posT, WVc_w, WVc_b, wvc, S2 * LK);

    // fused cross attention (split-KV) + combine into final layout
    flash_cross<<<dim3(LQ / 128, S2, NSPLIT), 256, FSM_BYTES>>>(wqc, wkc, wvc, po, pl);
    combine_out<<<(S2 * CE * HW) / 256, 256>>>(po, pl, out);
}